// round 12
// baseline (speedup 1.0000x reference)
#include <cuda_runtime.h>
#include <cuda_bf16.h>
#include <math.h>

#define NMAX 50000
#define NPAD 50048          // 391 tiles of 128
#define EMAX 800000
#define HD   128

// Scratch (device globals — no allocation allowed)
__device__ __align__(16) unsigned long long g_pk[NMAX];   // packed cnt<<42 | sum(ew)*2^24
__device__ __align__(16) float g_dinv[NMAX];
__device__ __align__(16) int   g_cnt[NMAX];
__device__ __align__(16) int   g_off[NMAX];
__device__ __align__(16) int2  g_meta[NMAX];              // (off, cnt)
__device__ __align__(16) int   g_head[NMAX];
__device__ __align__(16) int   g_bsum[256];
__device__ __align__(16) int2  g_csr_edge[EMAX];          // (src, bitcast(norm_w))
__device__ __align__(16) float g_h[(size_t)NPAD * HD];    // GEMM output
__device__ __align__(16) float g_agg[(size_t)NPAD * HD];  // aggregation / layer output
// Pre-swizzled bf16 weight panels, BK=32 chunks of 128x80B.
__device__ __align__(16) unsigned char g_wp_hi[163840];
__device__ __align__(16) unsigned char g_wp_lo[163840];

// ---------------------------------------------------------------------------
__device__ __forceinline__ unsigned smem_u32(const void* p) {
    unsigned a;
    asm("{ .reg .u64 t; cvta.to.shared.u64 t, %1; cvt.u32.u64 %0, t; }" : "=r"(a) : "l"(p));
    return a;
}
__device__ __forceinline__ void ldsm4(unsigned* r, unsigned addr) {
    asm volatile("ldmatrix.sync.aligned.m8n8.x4.shared.b16 {%0,%1,%2,%3}, [%4];"
                 : "=r"(r[0]), "=r"(r[1]), "=r"(r[2]), "=r"(r[3]) : "r"(addr));
}
__device__ __forceinline__ void mma16816(float* c, const unsigned* a, unsigned b0, unsigned b1) {
    asm volatile("mma.sync.aligned.m16n8k16.row.col.f32.bf16.bf16.f32 "
                 "{%0,%1,%2,%3}, {%4,%5,%6,%7}, {%8,%9}, {%0,%1,%2,%3};"
                 : "+f"(c[0]), "+f"(c[1]), "+f"(c[2]), "+f"(c[3])
                 : "r"(a[0]), "r"(a[1]), "r"(a[2]), "r"(a[3]), "r"(b0), "r"(b1));
}
__device__ __forceinline__ void cpasync16(unsigned saddr, const void* gaddr) {
    asm volatile("cp.async.cg.shared.global [%0], [%1], 16;" :: "r"(saddr), "l"(gaddr));
}
#define CP_COMMIT() asm volatile("cp.async.commit_group;" ::: "memory")
#define CP_WAIT()   asm volatile("cp.async.wait_group 0;" ::: "memory")

__device__ __forceinline__ unsigned chunk_off(int row, int k) {
    return (unsigned)(row * 80 + k * 2);
}

// ---------------------------------------------------------------------------
__global__ void k_initp(unsigned long long* __restrict__ pk, int n) {
    int i = blockIdx.x * blockDim.x + threadIdx.x;
    if (i < n) pk[i] = 0ull;
}

// one 64-bit atomic per edge: count in bits [42..), fixed-point ew sum below
__global__ void k_hist(const int* __restrict__ dst, const float* __restrict__ ew,
                       unsigned long long* __restrict__ pk, int E) {
    int e = blockIdx.x * blockDim.x + threadIdx.x;
    if (e < E) {
        unsigned long long v = (1ull << 42)
            | (unsigned long long)(ew[e] * 16777216.0f);
        atomicAdd(&pk[dst[e]], v);
    }
}

__global__ void k_dinv(const unsigned long long* __restrict__ pk,
                       float* __restrict__ dinv, int* __restrict__ cnt, int n) {
    int i = blockIdx.x * blockDim.x + threadIdx.x;
    if (i < n) {
        unsigned long long v = pk[i];
        cnt[i] = (int)(v >> 42);
        float deg = 1.0f + (float)(v & 0x3FFFFFFFFFFull) * (1.0f / 16777216.0f);
        dinv[i] = rsqrtf(deg);   // deg >= 1 always
    }
}

__global__ void k_scan1(const int* __restrict__ cnt, int* __restrict__ off,
                        int* __restrict__ bsum, int n) {
    __shared__ int s[256];
    int i = blockIdx.x * 256 + threadIdx.x;
    int v = (i < n) ? cnt[i] : 0;
    s[threadIdx.x] = v;
    __syncthreads();
    for (int d = 1; d < 256; d <<= 1) {
        int t = (threadIdx.x >= d) ? s[threadIdx.x - d] : 0;
        __syncthreads();
        s[threadIdx.x] += t;
        __syncthreads();
    }
    if (i < n) off[i] = s[threadIdx.x] - v;
    if (threadIdx.x == 255) bsum[blockIdx.x] = s[255];
}

__global__ void k_scan2(int* __restrict__ bsum, int nb) {
    __shared__ int s[256];
    int t = threadIdx.x;
    int v = (t < nb) ? bsum[t] : 0;
    s[t] = v;
    __syncthreads();
    for (int d = 1; d < 256; d <<= 1) {
        int u = (t >= d) ? s[t - d] : 0;
        __syncthreads();
        s[t] += u;
        __syncthreads();
    }
    if (t < nb) bsum[t] = s[t] - v;
}

__global__ void k_scan3(const int* __restrict__ bsum, const int* __restrict__ cnt,
                        int* __restrict__ off, int* __restrict__ head,
                        int2* __restrict__ meta, int n) {
    int i = blockIdx.x * 256 + threadIdx.x;
    if (i < n) {
        int o = off[i] + bsum[blockIdx.x];
        off[i] = o;
        head[i] = o;
        meta[i] = make_int2(o, cnt[i]);
    }
}

__global__ void k_fill(const int* __restrict__ src, const int* __restrict__ dst,
                       const float* __restrict__ ew, const float* __restrict__ dinv,
                       int* __restrict__ head, int2* __restrict__ csr_edge, int E) {
    int e = blockIdx.x * blockDim.x + threadIdx.x;
    if (e < E) {
        int s = src[e], d = dst[e];
        int p = atomicAdd(&head[d], 1);
        csr_edge[p] = make_int2(s, __float_as_int(dinv[s] * ew[e]));
    }
}

// ---------------------------------------------------------------------------
__global__ void k_wconv(const float* __restrict__ W, unsigned char* __restrict__ hi,
                        unsigned char* __restrict__ lo, int K) {
    int e = blockIdx.x * 256 + threadIdx.x;
    if (e >= K * 128) return;
    int k = e >> 7, n = e & 127;
    float x = W[e];
    __nv_bfloat16 h = __float2bfloat16(x);
    __nv_bfloat16 l = __float2bfloat16(x - __bfloat162float(h));
    unsigned so = (unsigned)(k >> 5) * 10240u + chunk_off(n, k & 31);
    *(__nv_bfloat16*)(hi + so) = h;
    *(__nv_bfloat16*)(lo + so) = l;
}

// ---------------------------------------------------------------------------
// mma.sync bf16-split GEMM: C[NPAD,128] = A[*,K] @ W[K,128].
__global__ __launch_bounds__(256) void k_gemm_mma(
    const float* __restrict__ A, const unsigned char* __restrict__ wp_hi,
    const unsigned char* __restrict__ wp_lo, float* __restrict__ C, int Mreal, int K) {
    extern __shared__ __align__(16) unsigned char smem[];
    const unsigned sbase = smem_u32(smem);

    const int tid  = threadIdx.x;
    const int wid  = tid >> 5;
    const int lane = tid & 31;
    const int wm   = wid >> 2;
    const int wn   = wid & 3;
    const int m0   = blockIdx.x * 128;

    float acc[4][4][4];
#pragma unroll
    for (int i = 0; i < 4; i++)
#pragma unroll
        for (int j = 0; j < 4; j++)
#pragma unroll
            for (int r = 0; r < 4; r++) acc[i][j][r] = 0.0f;

    const int nst = K >> 5;

    auto issueB = [&](int buf, int kc) {
        const unsigned bh = sbase + buf * 40960 + 20480;
        const unsigned bl = bh + 10240;
        const unsigned char* gh = wp_hi + (size_t)kc * 10240;
        const unsigned char* gl = wp_lo + (size_t)kc * 10240;
        for (int i = tid; i < 640; i += 256) {
            cpasync16(bh + i * 16, gh + i * 16);
            cpasync16(bl + i * 16, gl + i * 16);
        }
        CP_COMMIT();
    };
    auto loadAregs = [&](int kc, float4* v) {
#pragma unroll
        for (int it = 0; it < 4; it++) {
            int f4 = it * 256 + tid;
            int row = f4 >> 3, kl = (f4 & 7) << 2;
            int gr = m0 + row;
            v[it] = make_float4(0.f, 0.f, 0.f, 0.f);
            if (gr < Mreal)
                v[it] = *(const float4*)(A + (size_t)gr * K + (kc << 5) + kl);
        }
    };
    auto storeA = [&](int buf, const float4* v) {
        unsigned char* bp = smem + buf * 40960;
#pragma unroll
        for (int it = 0; it < 4; it++) {
            int f4 = it * 256 + tid;
            int row = f4 >> 3, kl = (f4 & 7) << 2;
            float4 x = v[it];
            __nv_bfloat16 hx = __float2bfloat16(x.x), hy = __float2bfloat16(x.y);
            __nv_bfloat16 hz = __float2bfloat16(x.z), hw = __float2bfloat16(x.w);
            __nv_bfloat16 lx = __float2bfloat16(x.x - __bfloat162float(hx));
            __nv_bfloat16 ly = __float2bfloat16(x.y - __bfloat162float(hy));
            __nv_bfloat16 lz = __float2bfloat16(x.z - __bfloat162float(hz));
            __nv_bfloat16 lw = __float2bfloat16(x.w - __bfloat162float(hw));
            unsigned h0 = (unsigned)__bfloat16_as_ushort(hx) | ((unsigned)__bfloat16_as_ushort(hy) << 16);
            unsigned h1 = (unsigned)__bfloat16_as_ushort(hz) | ((unsigned)__bfloat16_as_ushort(hw) << 16);
            unsigned l0 = (unsigned)__bfloat16_as_ushort(lx) | ((unsigned)__bfloat16_as_ushort(ly) << 16);
            unsigned l1 = (unsigned)__bfloat16_as_ushort(lz) | ((unsigned)__bfloat16_as_ushort(lw) << 16);
            unsigned off = chunk_off(row, kl);
            *(uint2*)(bp + off)         = make_uint2(h0, h1);
            *(uint2*)(bp + 10240 + off) = make_uint2(l0, l1);
        }
    };
    auto compute = [&](int buf) {
        const unsigned aH = sbase + buf * 40960;
        const unsigned aL = aH + 10240;
        const unsigned bH = aH + 20480;
        const unsigned bL = aH + 30720;
        const int rsel = lane & 15;
        const unsigned koff16 = ((lane >> 4) << 4);
#pragma unroll
        for (int s = 0; s < 2; s++) {
            const unsigned kb = (unsigned)(s * 32) + koff16;
            unsigned ah[4][4], al[4][4], bh[2][4], bl[2][4];
#pragma unroll
            for (int mi = 0; mi < 4; mi++) {
                unsigned ro = chunk_off(wm * 64 + mi * 16 + rsel, 0) + kb;
                ldsm4(ah[mi], aH + ro);
                ldsm4(al[mi], aL + ro);
            }
#pragma unroll
            for (int g = 0; g < 2; g++) {
                unsigned ro = chunk_off(wn * 32 + g * 16 + rsel, 0) + kb;
                ldsm4(bh[g], bH + ro);
                ldsm4(bl[g], bL + ro);
            }
#pragma unroll
            for (int mi = 0; mi < 4; mi++)
#pragma unroll
                for (int nj = 0; nj < 4; nj++) {
                    int g = nj >> 1, o = nj & 1;
                    mma16816(acc[mi][nj], ah[mi], bh[g][o], bh[g][o + 2]);
                    mma16816(acc[mi][nj], ah[mi], bl[g][o], bl[g][o + 2]);
                    mma16816(acc[mi][nj], al[mi], bh[g][o], bh[g][o + 2]);
                }
        }
    };

    float4 stage[4];
    issueB(0, 0);
    loadAregs(0, stage);
    storeA(0, stage);
    CP_WAIT();
    __syncthreads();

    for (int kc = 0; kc < nst; kc++) {
        const int cur = kc & 1, nxt = cur ^ 1;
        const bool more = (kc + 1 < nst);
        if (more) {
            issueB(nxt, kc + 1);
            loadAregs(kc + 1, stage);
        }
        compute(cur);
        if (more) {
            storeA(nxt, stage);
            CP_WAIT();
        }
        __syncthreads();
    }

#pragma unroll
    for (int mi = 0; mi < 4; mi++) {
        int gm = m0 + wm * 64 + mi * 16 + (lane >> 2);
#pragma unroll
        for (int nj = 0; nj < 4; nj++) {
            int col = wn * 32 + nj * 8 + (lane & 3) * 2;
            *(float2*)(C + (size_t)gm * 128 + col)       = make_float2(acc[mi][nj][0], acc[mi][nj][1]);
            *(float2*)(C + (size_t)(gm + 8) * 128 + col) = make_float2(acc[mi][nj][2], acc[mi][nj][3]);
        }
    }
}

// ---------------------------------------------------------------------------
// Core per-node aggregate. One broadcast __ldg(int2) per edge; 8-edge
// unrolled gathers for deep MLP (hides L2 latency).
__device__ __forceinline__ float4 agg_node(
    const float* __restrict__ h, const int2* __restrict__ meta,
    const int2* __restrict__ csr_edge, const float* __restrict__ dinv,
    const float* __restrict__ bias, int node, int lane) {
    const float di = dinv[node];
    float4 acc = *(const float4*)(h + (size_t)node * HD + lane * 4);
    acc.x *= di; acc.y *= di; acc.z *= di; acc.w *= di;

    const int2 mt  = __ldg(meta + node);
    const int base = mt.x;
    const int m    = mt.y;
    int j = 0;
    for (; j + 8 <= m; j += 8) {
        int2 e0 = __ldg(csr_edge + base + j + 0);
        int2 e1 = __ldg(csr_edge + base + j + 1);
        int2 e2 = __ldg(csr_edge + base + j + 2);
        int2 e3 = __ldg(csr_edge + base + j + 3);
        int2 e4 = __ldg(csr_edge + base + j + 4);
        int2 e5 = __ldg(csr_edge + base + j + 5);
        int2 e6 = __ldg(csr_edge + base + j + 6);
        int2 e7 = __ldg(csr_edge + base + j + 7);
        float4 v0 = *(const float4*)(h + (size_t)e0.x * HD + lane * 4);
        float4 v1 = *(const float4*)(h + (size_t)e1.x * HD + lane * 4);
        float4 v2 = *(const float4*)(h + (size_t)e2.x * HD + lane * 4);
        float4 v3 = *(const float4*)(h + (size_t)e3.x * HD + lane * 4);
        float4 v4 = *(const float4*)(h + (size_t)e4.x * HD + lane * 4);
        float4 v5 = *(const float4*)(h + (size_t)e5.x * HD + lane * 4);
        float4 v6 = *(const float4*)(h + (size_t)e6.x * HD + lane * 4);
        float4 v7 = *(const float4*)(h + (size_t)e7.x * HD + lane * 4);
        float w0 = __int_as_float(e0.y), w1 = __int_as_float(e1.y);
        float w2 = __int_as_float(e2.y), w3 = __int_as_float(e3.y);
        float w4 = __int_as_float(e4.y), w5 = __int_as_float(e5.y);
        float w6 = __int_as_float(e6.y), w7 = __int_as_float(e7.y);
        acc.x = fmaf(w0, v0.x, acc.x); acc.y = fmaf(w0, v0.y, acc.y);
        acc.z = fmaf(w0, v0.z, acc.z); acc.w = fmaf(w0, v0.w, acc.w);
        acc.x = fmaf(w1, v1.x, acc.x); acc.y = fmaf(w1, v1.y, acc.y);
        acc.z = fmaf(w1, v1.z, acc.z); acc.w = fmaf(w1, v1.w, acc.w);
        acc.x = fmaf(w2, v2.x, acc.x); acc.y = fmaf(w2, v2.y, acc.y);
        acc.z = fmaf(w2, v2.z, acc.z); acc.w = fmaf(w2, v2.w, acc.w);
        acc.x = fmaf(w3, v3.x, acc.x); acc.y = fmaf(w3, v3.y, acc.y);
        acc.z = fmaf(w3, v3.z, acc.z); acc.w = fmaf(w3, v3.w, acc.w);
        acc.x = fmaf(w4, v4.x, acc.x); acc.y = fmaf(w4, v4.y, acc.y);
        acc.z = fmaf(w4, v4.z, acc.z); acc.w = fmaf(w4, v4.w, acc.w);
        acc.x = fmaf(w5, v5.x, acc.x); acc.y = fmaf(w5, v5.y, acc.y);
        acc.z = fmaf(w5, v5.z, acc.z); acc.w = fmaf(w5, v5.w, acc.w);
        acc.x = fmaf(w6, v6.x, acc.x); acc.y = fmaf(w6, v6.y, acc.y);
        acc.z = fmaf(w6, v6.z, acc.z); acc.w = fmaf(w6, v6.w, acc.w);
        acc.x = fmaf(w7, v7.x, acc.x); acc.y = fmaf(w7, v7.y, acc.y);
        acc.z = fmaf(w7, v7.z, acc.z); acc.w = fmaf(w7, v7.w, acc.w);
    }
    for (; j < m; j++) {
        int2 e = __ldg(csr_edge + base + j);
        float wj = __int_as_float(e.y);
        float4 v = *(const float4*)(h + (size_t)e.x * HD + lane * 4);
        acc.x = fmaf(wj, v.x, acc.x); acc.y = fmaf(wj, v.y, acc.y);
        acc.z = fmaf(wj, v.z, acc.z); acc.w = fmaf(wj, v.w, acc.w);
    }
    float4 bb = ((const float4*)bias)[lane];
    acc.x = fmaxf(fmaf(di, acc.x, bb.x), 0.0f);
    acc.y = fmaxf(fmaf(di, acc.y, bb.y), 0.0f);
    acc.z = fmaxf(fmaf(di, acc.z, bb.z), 0.0f);
    acc.w = fmaxf(fmaf(di, acc.w, bb.w), 0.0f);
    return acc;
}

// aggregation, full node range
__global__ void k_agg(const float* __restrict__ h, const int2* __restrict__ meta,
                      const int2* __restrict__ csr_edge, const float* __restrict__ dinv,
                      const float* __restrict__ bias, float* __restrict__ outp, int n) {
    int node = blockIdx.x * (blockDim.x >> 5) + (threadIdx.x >> 5);
    int lane = threadIdx.x & 31;
    if (node >= n) return;
    float4 acc = agg_node(h, meta, csr_edge, dinv, bias, node, lane);
    *(float4*)(outp + (size_t)node * HD + lane * 4) = acc;
}

// layer-3 aggregation fused with FC head + softmax
__global__ void k_agg_head(const float* __restrict__ h, const int2* __restrict__ meta,
                           const int2* __restrict__ csr_edge, const float* __restrict__ dinv,
                           const float* __restrict__ bias, const float* __restrict__ fcw,
                           const float* __restrict__ fcb, float* __restrict__ out, int n) {
    __shared__ float sw[HD * 10];
    __shared__ float sb[10];
    for (int i = threadIdx.x; i < HD * 10; i += blockDim.x) sw[i] = fcw[i];
    if (threadIdx.x < 10) sb[threadIdx.x] = fcb[threadIdx.x];
    __syncthreads();

    int node = blockIdx.x * (blockDim.x >> 5) + (threadIdx.x >> 5);
    int lane = threadIdx.x & 31;
    if (node >= n) return;
    float4 acc = agg_node(h, meta, csr_edge, dinv, bias, node, lane);

    int k = lane * 4;
    float part[10];
#pragma unroll
    for (int c = 0; c < 10; c++) {
        part[c] = acc.x * sw[(k + 0) * 10 + c] + acc.y * sw[(k + 1) * 10 + c]
                + acc.z * sw[(k + 2) * 10 + c] + acc.w * sw[(k + 3) * 10 + c];
    }
#pragma unroll
    for (int o = 16; o; o >>= 1)
#pragma unroll
        for (int c = 0; c < 10; c++)
            part[c] += __shfl_xor_sync(0xffffffffu, part[c], o);
    if (lane == 0) {
        float m = -1e30f;
#pragma unroll
        for (int c = 0; c < 10; c++) { part[c] += sb[c]; m = fmaxf(m, part[c]); }
        float s = 0.0f;
#pragma unroll
        for (int c = 0; c < 10; c++) { part[c] = expf(part[c] - m); s += part[c]; }
        float inv = 1.0f / s;
#pragma unroll
        for (int c = 0; c < 10; c++) out[(size_t)node * 10 + c] = part[c] * inv;
    }
}

// ---------------------------------------------------------------------------
extern "C" void kernel_launch(void* const* d_in, const int* in_sizes, int n_in,
                              void* d_out, int out_size) {
    const float* x   = (const float*)d_in[0];
    const int*   ei  = (const int*)d_in[1];
    const float* ew  = (const float*)d_in[2];
    const float* W1  = (const float*)d_in[3];
    const float* b1  = (const float*)d_in[4];
    const float* W2  = (const float*)d_in[5];
    const float* b2  = (const float*)d_in[6];
    const float* W3  = (const float*)d_in[7];
    const float* b3  = (const float*)d_in[8];
    const float* fcw = (const float*)d_in[9];
    const float* fcb = (const float*)d_in[10];
    float* out = (float*)d_out;

    const int H = in_sizes[4];              // 128
    const int F = in_sizes[3] / H;          // 256
    const int N = in_sizes[0] / F;          // 50000
    const int E = in_sizes[2];              // 800000
    (void)n_in; (void)out_size;

    const int* src = ei;
    const int* dst = ei + E;

    unsigned long long* pk; cudaGetSymbolAddress((void**)&pk, g_pk);
    float* dinv; cudaGetSymbolAddress((void**)&dinv, g_dinv);
    int*   cnt;  cudaGetSymbolAddress((void**)&cnt,  g_cnt);
    int*   off;  cudaGetSymbolAddress((void**)&off,  g_off);
    int2*  meta; cudaGetSymbolAddress((void**)&meta, g_meta);
    int*   head; cudaGetSymbolAddress((void**)&head, g_head);
    int*   bsum; cudaGetSymbolAddress((void**)&bsum, g_bsum);
    int2*  cedge; cudaGetSymbolAddress((void**)&cedge, g_csr_edge);
    float* hbuf; cudaGetSymbolAddress((void**)&hbuf, g_h);
    float* agg;  cudaGetSymbolAddress((void**)&agg,  g_agg);
    unsigned char* wph; cudaGetSymbolAddress((void**)&wph, g_wp_hi);
    unsigned char* wpl; cudaGetSymbolAddress((void**)&wpl, g_wp_lo);

    const int SMEM_GEMM = 81920;
    static cudaStream_t s2 = 0;
    static cudaEvent_t evRoot = 0, evPre = 0;
    if (!s2) {
        cudaFuncSetAttribute(k_gemm_mma, cudaFuncAttributeMaxDynamicSharedMemorySize, SMEM_GEMM);
        cudaStreamCreateWithFlags(&s2, cudaStreamNonBlocking);
        cudaEventCreateWithFlags(&evRoot, cudaEventDisableTiming);
        cudaEventCreateWithFlags(&evPre, cudaEventDisableTiming);
    }

    const int T = 256;
    const int scan_blocks = (N + 255) / 256;
    const int agg_blocks  = (N + 7) / 8;
    const int gemm_blocks = NPAD / 128;   // 391

    // ---- fork: CSR precompute on side stream, overlapped with wconv+GEMM1 ----
    cudaEventRecord(evRoot, 0);
    cudaStreamWaitEvent(s2, evRoot, 0);

    k_initp<<<(N + T - 1) / T, T, 0, s2>>>(pk, N);
    k_hist <<<(E + T - 1) / T, T, 0, s2>>>(dst, ew, pk, E);
    k_dinv <<<(N + T - 1) / T, T, 0, s2>>>(pk, dinv, cnt, N);
    k_scan1<<<scan_blocks, 256, 0, s2>>>(cnt, off, bsum, N);
    k_scan2<<<1, 256, 0, s2>>>(bsum, scan_blocks);
    k_scan3<<<scan_blocks, 256, 0, s2>>>(bsum, cnt, off, head, meta, N);
    k_fill <<<(E + T - 1) / T, T, 0, s2>>>(src, dst, ew, dinv, head, cedge, E);
    cudaEventRecord(evPre, s2);

    // main stream: weight conversion + layer-1 GEMM (independent of CSR)
    k_wconv<<<(F * 128 + 255) / 256, 256>>>(W1, wph,          wpl,          F);
    k_wconv<<<(H * 128 + 255) / 256, 256>>>(W2, wph + 81920,  wpl + 81920,  H);
    k_wconv<<<(H * 128 + 255) / 256, 256>>>(W3, wph + 122880, wpl + 122880, H);
    k_gemm_mma<<<gemm_blocks, 256, SMEM_GEMM>>>(x, wph, wpl, hbuf, N, F);

    // ---- join: aggregation needs the CSR ----
    cudaStreamWaitEvent(0, evPre, 0);

    // layer 1
    k_agg<<<agg_blocks, 256>>>(hbuf, meta, cedge, dinv, b1, agg, N);
    // layer 2
    k_gemm_mma<<<gemm_blocks, 256, SMEM_GEMM>>>(agg, wph + 81920, wpl + 81920, hbuf, NPAD, H);
    k_agg<<<agg_blocks, 256>>>(hbuf, meta, cedge, dinv, b2, agg, N);
    // layer 3
    k_gemm_mma<<<gemm_blocks, 256, SMEM_GEMM>>>(agg, wph + 122880, wpl + 122880, hbuf, NPAD, H);
    // layer-3 agg fused with FC head + softmax
    k_agg_head<<<agg_blocks, 256>>>(hbuf, meta, cedge, dinv, b3, fcw, fcb, out, N);
}

// round 14
// speedup vs baseline: 1.1413x; 1.1413x over previous
#include <cuda_runtime.h>
#include <cuda_bf16.h>
#include <cuda_fp16.h>
#include <math.h>

#define NMAX 50000
#define NPAD 50048          // 391 tiles of 128
#define EMAX 800000
#define HD   128

// Scratch (device globals — no allocation allowed)
__device__ __align__(16) unsigned long long g_pk[NMAX];   // packed cnt<<42 | sum(ew)*2^24
__device__ __align__(16) float g_dinv[NMAX];
__device__ __align__(16) int   g_cnt[NMAX];
__device__ __align__(16) int   g_off[NMAX];
__device__ __align__(16) int2  g_meta[NMAX];              // (off, cnt)
__device__ __align__(16) int   g_head[NMAX];
__device__ __align__(16) int   g_bsum[256];
__device__ __align__(16) int2  g_csr_edge[EMAX];          // (src, bitcast(norm_w))
__device__ __align__(16) __half g_h[(size_t)NPAD * HD];   // GEMM output (fp16 storage)
__device__ __align__(16) float  g_agg[(size_t)NPAD * HD]; // aggregation / layer output
// Pre-swizzled bf16 weight panels, BK=32 chunks of 128x80B.
__device__ __align__(16) unsigned char g_wp_hi[163840];
__device__ __align__(16) unsigned char g_wp_lo[163840];

// ---------------------------------------------------------------------------
__device__ __forceinline__ unsigned smem_u32(const void* p) {
    unsigned a;
    asm("{ .reg .u64 t; cvta.to.shared.u64 t, %1; cvt.u32.u64 %0, t; }" : "=r"(a) : "l"(p));
    return a;
}
__device__ __forceinline__ void ldsm4(unsigned* r, unsigned addr) {
    asm volatile("ldmatrix.sync.aligned.m8n8.x4.shared.b16 {%0,%1,%2,%3}, [%4];"
                 : "=r"(r[0]), "=r"(r[1]), "=r"(r[2]), "=r"(r[3]) : "r"(addr));
}
__device__ __forceinline__ void mma16816(float* c, const unsigned* a, unsigned b0, unsigned b1) {
    asm volatile("mma.sync.aligned.m16n8k16.row.col.f32.bf16.bf16.f32 "
                 "{%0,%1,%2,%3}, {%4,%5,%6,%7}, {%8,%9}, {%0,%1,%2,%3};"
                 : "+f"(c[0]), "+f"(c[1]), "+f"(c[2]), "+f"(c[3])
                 : "r"(a[0]), "r"(a[1]), "r"(a[2]), "r"(a[3]), "r"(b0), "r"(b1));
}
__device__ __forceinline__ void cpasync16(unsigned saddr, const void* gaddr) {
    asm volatile("cp.async.cg.shared.global [%0], [%1], 16;" :: "r"(saddr), "l"(gaddr));
}
#define CP_COMMIT() asm volatile("cp.async.commit_group;" ::: "memory")
#define CP_WAIT()   asm volatile("cp.async.wait_group 0;" ::: "memory")

__device__ __forceinline__ unsigned chunk_off(int row, int k) {
    return (unsigned)(row * 80 + k * 2);
}
// unpack 4 packed halves -> float4
__device__ __forceinline__ float4 h4f(uint2 u) {
    __half2 p0 = *reinterpret_cast<__half2*>(&u.x);
    __half2 p1 = *reinterpret_cast<__half2*>(&u.y);
    float2 f0 = __half22float2(p0), f1 = __half22float2(p1);
    return make_float4(f0.x, f0.y, f1.x, f1.y);
}

// ---------------------------------------------------------------------------
__global__ void k_initp(unsigned long long* __restrict__ pk, int n) {
    int i = blockIdx.x * blockDim.x + threadIdx.x;
    if (i < n) pk[i] = 0ull;
}

// one 64-bit atomic per edge: count in bits [42..), fixed-point ew sum below
__global__ void k_hist(const int* __restrict__ dst, const float* __restrict__ ew,
                       unsigned long long* __restrict__ pk, int E) {
    int e = blockIdx.x * blockDim.x + threadIdx.x;
    if (e < E) {
        unsigned long long v = (1ull << 42)
            | (unsigned long long)(ew[e] * 16777216.0f);
        atomicAdd(&pk[dst[e]], v);
    }
}

__global__ void k_dinv(const unsigned long long* __restrict__ pk,
                       float* __restrict__ dinv, int* __restrict__ cnt, int n) {
    int i = blockIdx.x * blockDim.x + threadIdx.x;
    if (i < n) {
        unsigned long long v = pk[i];
        cnt[i] = (int)(v >> 42);
        float deg = 1.0f + (float)(v & 0x3FFFFFFFFFFull) * (1.0f / 16777216.0f);
        dinv[i] = rsqrtf(deg);   // deg >= 1 always
    }
}

__global__ void k_scan1(const int* __restrict__ cnt, int* __restrict__ off,
                        int* __restrict__ bsum, int n) {
    __shared__ int s[256];
    int i = blockIdx.x * 256 + threadIdx.x;
    int v = (i < n) ? cnt[i] : 0;
    s[threadIdx.x] = v;
    __syncthreads();
    for (int d = 1; d < 256; d <<= 1) {
        int t = (threadIdx.x >= d) ? s[threadIdx.x - d] : 0;
        __syncthreads();
        s[threadIdx.x] += t;
        __syncthreads();
    }
    if (i < n) off[i] = s[threadIdx.x] - v;
    if (threadIdx.x == 255) bsum[blockIdx.x] = s[255];
}

__global__ void k_scan2(int* __restrict__ bsum, int nb) {
    __shared__ int s[256];
    int t = threadIdx.x;
    int v = (t < nb) ? bsum[t] : 0;
    s[t] = v;
    __syncthreads();
    for (int d = 1; d < 256; d <<= 1) {
        int u = (t >= d) ? s[t - d] : 0;
        __syncthreads();
        s[t] += u;
        __syncthreads();
    }
    if (t < nb) bsum[t] = s[t] - v;
}

__global__ void k_scan3(const int* __restrict__ bsum, const int* __restrict__ cnt,
                        int* __restrict__ off, int* __restrict__ head,
                        int2* __restrict__ meta, int n) {
    int i = blockIdx.x * 256 + threadIdx.x;
    if (i < n) {
        int o = off[i] + bsum[blockIdx.x];
        off[i] = o;
        head[i] = o;
        meta[i] = make_int2(o, cnt[i]);
    }
}

__global__ void k_fill(const int* __restrict__ src, const int* __restrict__ dst,
                       const float* __restrict__ ew, const float* __restrict__ dinv,
                       int* __restrict__ head, int2* __restrict__ csr_edge, int E) {
    int e = blockIdx.x * blockDim.x + threadIdx.x;
    if (e < E) {
        int s = src[e], d = dst[e];
        int p = atomicAdd(&head[d], 1);
        csr_edge[p] = make_int2(s, __float_as_int(dinv[s] * ew[e]));
    }
}

// ---------------------------------------------------------------------------
__global__ void k_wconv(const float* __restrict__ W, unsigned char* __restrict__ hi,
                        unsigned char* __restrict__ lo, int K) {
    int e = blockIdx.x * 256 + threadIdx.x;
    if (e >= K * 128) return;
    int k = e >> 7, n = e & 127;
    float x = W[e];
    __nv_bfloat16 h = __float2bfloat16(x);
    __nv_bfloat16 l = __float2bfloat16(x - __bfloat162float(h));
    unsigned so = (unsigned)(k >> 5) * 10240u + chunk_off(n, k & 31);
    *(__nv_bfloat16*)(hi + so) = h;
    *(__nv_bfloat16*)(lo + so) = l;
}

// ---------------------------------------------------------------------------
// mma.sync bf16-split GEMM: C[NPAD,128] (fp16) = A[*,K] (fp32) @ W[K,128].
__global__ __launch_bounds__(256) void k_gemm_mma(
    const float* __restrict__ A, const unsigned char* __restrict__ wp_hi,
    const unsigned char* __restrict__ wp_lo, __half* __restrict__ C, int Mreal, int K) {
    extern __shared__ __align__(16) unsigned char smem[];
    const unsigned sbase = smem_u32(smem);

    const int tid  = threadIdx.x;
    const int wid  = tid >> 5;
    const int lane = tid & 31;
    const int wm   = wid >> 2;
    const int wn   = wid & 3;
    const int m0   = blockIdx.x * 128;

    float acc[4][4][4];
#pragma unroll
    for (int i = 0; i < 4; i++)
#pragma unroll
        for (int j = 0; j < 4; j++)
#pragma unroll
            for (int r = 0; r < 4; r++) acc[i][j][r] = 0.0f;

    const int nst = K >> 5;

    auto issueB = [&](int buf, int kc) {
        const unsigned bh = sbase + buf * 40960 + 20480;
        const unsigned bl = bh + 10240;
        const unsigned char* gh = wp_hi + (size_t)kc * 10240;
        const unsigned char* gl = wp_lo + (size_t)kc * 10240;
        for (int i = tid; i < 640; i += 256) {
            cpasync16(bh + i * 16, gh + i * 16);
            cpasync16(bl + i * 16, gl + i * 16);
        }
        CP_COMMIT();
    };
    auto loadAregs = [&](int kc, float4* v) {
#pragma unroll
        for (int it = 0; it < 4; it++) {
            int f4 = it * 256 + tid;
            int row = f4 >> 3, kl = (f4 & 7) << 2;
            int gr = m0 + row;
            v[it] = make_float4(0.f, 0.f, 0.f, 0.f);
            if (gr < Mreal)
                v[it] = *(const float4*)(A + (size_t)gr * K + (kc << 5) + kl);
        }
    };
    auto storeA = [&](int buf, const float4* v) {
        unsigned char* bp = smem + buf * 40960;
#pragma unroll
        for (int it = 0; it < 4; it++) {
            int f4 = it * 256 + tid;
            int row = f4 >> 3, kl = (f4 & 7) << 2;
            float4 x = v[it];
            __nv_bfloat16 hx = __float2bfloat16(x.x), hy = __float2bfloat16(x.y);
            __nv_bfloat16 hz = __float2bfloat16(x.z), hw = __float2bfloat16(x.w);
            __nv_bfloat16 lx = __float2bfloat16(x.x - __bfloat162float(hx));
            __nv_bfloat16 ly = __float2bfloat16(x.y - __bfloat162float(hy));
            __nv_bfloat16 lz = __float2bfloat16(x.z - __bfloat162float(hz));
            __nv_bfloat16 lw = __float2bfloat16(x.w - __bfloat162float(hw));
            unsigned h0 = (unsigned)__bfloat16_as_ushort(hx) | ((unsigned)__bfloat16_as_ushort(hy) << 16);
            unsigned h1 = (unsigned)__bfloat16_as_ushort(hz) | ((unsigned)__bfloat16_as_ushort(hw) << 16);
            unsigned l0 = (unsigned)__bfloat16_as_ushort(lx) | ((unsigned)__bfloat16_as_ushort(ly) << 16);
            unsigned l1 = (unsigned)__bfloat16_as_ushort(lz) | ((unsigned)__bfloat16_as_ushort(lw) << 16);
            unsigned off = chunk_off(row, kl);
            *(uint2*)(bp + off)         = make_uint2(h0, h1);
            *(uint2*)(bp + 10240 + off) = make_uint2(l0, l1);
        }
    };
    auto compute = [&](int buf) {
        const unsigned aH = sbase + buf * 40960;
        const unsigned aL = aH + 10240;
        const unsigned bH = aH + 20480;
        const unsigned bL = aH + 30720;
        const int rsel = lane & 15;
        const unsigned koff16 = ((lane >> 4) << 4);
#pragma unroll
        for (int s = 0; s < 2; s++) {
            const unsigned kb = (unsigned)(s * 32) + koff16;
            unsigned ah[4][4], al[4][4], bh[2][4], bl[2][4];
#pragma unroll
            for (int mi = 0; mi < 4; mi++) {
                unsigned ro = chunk_off(wm * 64 + mi * 16 + rsel, 0) + kb;
                ldsm4(ah[mi], aH + ro);
                ldsm4(al[mi], aL + ro);
            }
#pragma unroll
            for (int g = 0; g < 2; g++) {
                unsigned ro = chunk_off(wn * 32 + g * 16 + rsel, 0) + kb;
                ldsm4(bh[g], bH + ro);
                ldsm4(bl[g], bL + ro);
            }
#pragma unroll
            for (int mi = 0; mi < 4; mi++)
#pragma unroll
                for (int nj = 0; nj < 4; nj++) {
                    int g = nj >> 1, o = nj & 1;
                    mma16816(acc[mi][nj], ah[mi], bh[g][o], bh[g][o + 2]);
                    mma16816(acc[mi][nj], ah[mi], bl[g][o], bl[g][o + 2]);
                    mma16816(acc[mi][nj], al[mi], bh[g][o], bh[g][o + 2]);
                }
        }
    };

    float4 stage[4];
    issueB(0, 0);
    loadAregs(0, stage);
    storeA(0, stage);
    CP_WAIT();
    __syncthreads();

    for (int kc = 0; kc < nst; kc++) {
        const int cur = kc & 1, nxt = cur ^ 1;
        const bool more = (kc + 1 < nst);
        if (more) {
            issueB(nxt, kc + 1);
            loadAregs(kc + 1, stage);
        }
        compute(cur);
        if (more) {
            storeA(nxt, stage);
            CP_WAIT();
        }
        __syncthreads();
    }

    // epilogue: fp16 store, unguarded (C padded to NPAD rows)
#pragma unroll
    for (int mi = 0; mi < 4; mi++) {
        int gm = m0 + wm * 64 + mi * 16 + (lane >> 2);
#pragma unroll
        for (int nj = 0; nj < 4; nj++) {
            int col = wn * 32 + nj * 8 + (lane & 3) * 2;
            *(__half2*)(C + (size_t)gm * 128 + col)       = __floats2half2_rn(acc[mi][nj][0], acc[mi][nj][1]);
            *(__half2*)(C + (size_t)(gm + 8) * 128 + col) = __floats2half2_rn(acc[mi][nj][2], acc[mi][nj][3]);
        }
    }
}

// ---------------------------------------------------------------------------
// Core per-node aggregate over fp16 h. One broadcast __ldg(int2) per edge,
// 4-edge unrolled gathers; fp32 accumulation.
__device__ __forceinline__ float4 agg_node(
    const __half* __restrict__ h, const int2* __restrict__ meta,
    const int2* __restrict__ csr_edge, const float* __restrict__ dinv,
    const float* __restrict__ bias, int node, int lane) {
    const float di = dinv[node];
    float4 acc = h4f(*(const uint2*)(h + (size_t)node * HD + lane * 4));
    acc.x *= di; acc.y *= di; acc.z *= di; acc.w *= di;

    const int2 mt  = __ldg(meta + node);
    const int base = mt.x;
    const int m    = mt.y;
    int j = 0;
    for (; j + 4 <= m; j += 4) {
        int2 e0 = __ldg(csr_edge + base + j + 0);
        int2 e1 = __ldg(csr_edge + base + j + 1);
        int2 e2 = __ldg(csr_edge + base + j + 2);
        int2 e3 = __ldg(csr_edge + base + j + 3);
        uint2 u0 = __ldg((const uint2*)(h + (size_t)e0.x * HD + lane * 4));
        uint2 u1 = __ldg((const uint2*)(h + (size_t)e1.x * HD + lane * 4));
        uint2 u2 = __ldg((const uint2*)(h + (size_t)e2.x * HD + lane * 4));
        uint2 u3 = __ldg((const uint2*)(h + (size_t)e3.x * HD + lane * 4));
        float w0 = __int_as_float(e0.y), w1 = __int_as_float(e1.y);
        float w2 = __int_as_float(e2.y), w3 = __int_as_float(e3.y);
        float4 v0 = h4f(u0), v1 = h4f(u1), v2 = h4f(u2), v3 = h4f(u3);
        acc.x = fmaf(w0, v0.x, acc.x); acc.y = fmaf(w0, v0.y, acc.y);
        acc.z = fmaf(w0, v0.z, acc.z); acc.w = fmaf(w0, v0.w, acc.w);
        acc.x = fmaf(w1, v1.x, acc.x); acc.y = fmaf(w1, v1.y, acc.y);
        acc.z = fmaf(w1, v1.z, acc.z); acc.w = fmaf(w1, v1.w, acc.w);
        acc.x = fmaf(w2, v2.x, acc.x); acc.y = fmaf(w2, v2.y, acc.y);
        acc.z = fmaf(w2, v2.z, acc.z); acc.w = fmaf(w2, v2.w, acc.w);
        acc.x = fmaf(w3, v3.x, acc.x); acc.y = fmaf(w3, v3.y, acc.y);
        acc.z = fmaf(w3, v3.z, acc.z); acc.w = fmaf(w3, v3.w, acc.w);
    }
    for (; j < m; j++) {
        int2 e = __ldg(csr_edge + base + j);
        float wj = __int_as_float(e.y);
        float4 v = h4f(__ldg((const uint2*)(h + (size_t)e.x * HD + lane * 4)));
        acc.x = fmaf(wj, v.x, acc.x); acc.y = fmaf(wj, v.y, acc.y);
        acc.z = fmaf(wj, v.z, acc.z); acc.w = fmaf(wj, v.w, acc.w);
    }
    float4 bb = ((const float4*)bias)[lane];
    acc.x = fmaxf(fmaf(di, acc.x, bb.x), 0.0f);
    acc.y = fmaxf(fmaf(di, acc.y, bb.y), 0.0f);
    acc.z = fmaxf(fmaf(di, acc.z, bb.z), 0.0f);
    acc.w = fmaxf(fmaf(di, acc.w, bb.w), 0.0f);
    return acc;
}

// aggregation, full node range (fp32 output for GEMM A operand)
__global__ void k_agg(const __half* __restrict__ h, const int2* __restrict__ meta,
                      const int2* __restrict__ csr_edge, const float* __restrict__ dinv,
                      const float* __restrict__ bias, float* __restrict__ outp, int n) {
    int node = blockIdx.x * (blockDim.x >> 5) + (threadIdx.x >> 5);
    int lane = threadIdx.x & 31;
    if (node >= n) return;
    float4 acc = agg_node(h, meta, csr_edge, dinv, bias, node, lane);
    *(float4*)(outp + (size_t)node * HD + lane * 4) = acc;
}

// layer-3 aggregation fused with FC head + softmax
__global__ void k_agg_head(const __half* __restrict__ h, const int2* __restrict__ meta,
                           const int2* __restrict__ csr_edge, const float* __restrict__ dinv,
                           const float* __restrict__ bias, const float* __restrict__ fcw,
                           const float* __restrict__ fcb, float* __restrict__ out, int n) {
    __shared__ float sw[HD * 10];
    __shared__ float sb[10];
    for (int i = threadIdx.x; i < HD * 10; i += blockDim.x) sw[i] = fcw[i];
    if (threadIdx.x < 10) sb[threadIdx.x] = fcb[threadIdx.x];
    __syncthreads();

    int node = blockIdx.x * (blockDim.x >> 5) + (threadIdx.x >> 5);
    int lane = threadIdx.x & 31;
    if (node >= n) return;
    float4 acc = agg_node(h, meta, csr_edge, dinv, bias, node, lane);

    int k = lane * 4;
    float part[10];
#pragma unroll
    for (int c = 0; c < 10; c++) {
        part[c] = acc.x * sw[(k + 0) * 10 + c] + acc.y * sw[(k + 1) * 10 + c]
                + acc.z * sw[(k + 2) * 10 + c] + acc.w * sw[(k + 3) * 10 + c];
    }
#pragma unroll
    for (int o = 16; o; o >>= 1)
#pragma unroll
        for (int c = 0; c < 10; c++)
            part[c] += __shfl_xor_sync(0xffffffffu, part[c], o);
    if (lane == 0) {
        float m = -1e30f;
#pragma unroll
        for (int c = 0; c < 10; c++) { part[c] += sb[c]; m = fmaxf(m, part[c]); }
        float s = 0.0f;
#pragma unroll
        for (int c = 0; c < 10; c++) { part[c] = expf(part[c] - m); s += part[c]; }
        float inv = 1.0f / s;
#pragma unroll
        for (int c = 0; c < 10; c++) out[(size_t)node * 10 + c] = part[c] * inv;
    }
}

// ---------------------------------------------------------------------------
extern "C" void kernel_launch(void* const* d_in, const int* in_sizes, int n_in,
                              void* d_out, int out_size) {
    const float* x   = (const float*)d_in[0];
    const int*   ei  = (const int*)d_in[1];
    const float* ew  = (const float*)d_in[2];
    const float* W1  = (const float*)d_in[3];
    const float* b1  = (const float*)d_in[4];
    const float* W2  = (const float*)d_in[5];
    const float* b2  = (const float*)d_in[6];
    const float* W3  = (const float*)d_in[7];
    const float* b3  = (const float*)d_in[8];
    const float* fcw = (const float*)d_in[9];
    const float* fcb = (const float*)d_in[10];
    float* out = (float*)d_out;

    const int H = in_sizes[4];              // 128
    const int F = in_sizes[3] / H;          // 256
    const int N = in_sizes[0] / F;          // 50000
    const int E = in_sizes[2];              // 800000
    (void)n_in; (void)out_size;

    const int* src = ei;
    const int* dst = ei + E;

    unsigned long long* pk; cudaGetSymbolAddress((void**)&pk, g_pk);
    float* dinv; cudaGetSymbolAddress((void**)&dinv, g_dinv);
    int*   cnt;  cudaGetSymbolAddress((void**)&cnt,  g_cnt);
    int*   off;  cudaGetSymbolAddress((void**)&off,  g_off);
    int2*  meta; cudaGetSymbolAddress((void**)&meta, g_meta);
    int*   head; cudaGetSymbolAddress((void**)&head, g_head);
    int*   bsum; cudaGetSymbolAddress((void**)&bsum, g_bsum);
    int2*  cedge; cudaGetSymbolAddress((void**)&cedge, g_csr_edge);
    __half* hbuf; cudaGetSymbolAddress((void**)&hbuf, g_h);
    float* agg;  cudaGetSymbolAddress((void**)&agg,  g_agg);
    unsigned char* wph; cudaGetSymbolAddress((void**)&wph, g_wp_hi);
    unsigned char* wpl; cudaGetSymbolAddress((void**)&wpl, g_wp_lo);

    const int SMEM_GEMM = 81920;
    static cudaStream_t s2 = 0;
    static cudaEvent_t evRoot = 0, evPre = 0;
    if (!s2) {
        cudaFuncSetAttribute(k_gemm_mma, cudaFuncAttributeMaxDynamicSharedMemorySize, SMEM_GEMM);
        cudaStreamCreateWithFlags(&s2, cudaStreamNonBlocking);
        cudaEventCreateWithFlags(&evRoot, cudaEventDisableTiming);
        cudaEventCreateWithFlags(&evPre, cudaEventDisableTiming);
    }

    const int T = 256;
    const int scan_blocks = (N + 255) / 256;
    const int agg_blocks  = (N + 7) / 8;
    const int gemm_blocks = NPAD / 128;   // 391

    // ---- fork: CSR precompute on side stream, overlapped with wconv+GEMM1 ----
    cudaEventRecord(evRoot, 0);
    cudaStreamWaitEvent(s2, evRoot, 0);

    k_initp<<<(N + T - 1) / T, T, 0, s2>>>(pk, N);
    k_hist <<<(E + T - 1) / T, T, 0, s2>>>(dst, ew, pk, E);
    k_dinv <<<(N + T - 1) / T, T, 0, s2>>>(pk, dinv, cnt, N);
    k_scan1<<<scan_blocks, 256, 0, s2>>>(cnt, off, bsum, N);
    k_scan2<<<1, 256, 0, s2>>>(bsum, scan_blocks);
    k_scan3<<<scan_blocks, 256, 0, s2>>>(bsum, cnt, off, head, meta, N);
    k_fill <<<(E + T - 1) / T, T, 0, s2>>>(src, dst, ew, dinv, head, cedge, E);
    cudaEventRecord(evPre, s2);

    // main stream: weight conversion + layer-1 GEMM (independent of CSR)
    k_wconv<<<(F * 128 + 255) / 256, 256>>>(W1, wph,          wpl,          F);
    k_wconv<<<(H * 128 + 255) / 256, 256>>>(W2, wph + 81920,  wpl + 81920,  H);
    k_wconv<<<(H * 128 + 255) / 256, 256>>>(W3, wph + 122880, wpl + 122880, H);
    k_gemm_mma<<<gemm_blocks, 256, SMEM_GEMM>>>(x, wph, wpl, hbuf, N, F);

    // ---- join: aggregation needs the CSR ----
    cudaStreamWaitEvent(0, evPre, 0);

    // layer 1
    k_agg<<<agg_blocks, 256>>>(hbuf, meta, cedge, dinv, b1, agg, N);
    // layer 2
    k_gemm_mma<<<gemm_blocks, 256, SMEM_GEMM>>>(agg, wph + 81920, wpl + 81920, hbuf, NPAD, H);
    k_agg<<<agg_blocks, 256>>>(hbuf, meta, cedge, dinv, b2, agg, N);
    // layer 3
    k_gemm_mma<<<gemm_blocks, 256, SMEM_GEMM>>>(agg, wph + 122880, wpl + 122880, hbuf, NPAD, H);
    // layer-3 agg fused with FC head + softmax
    k_agg_head<<<agg_blocks, 256>>>(hbuf, meta, cedge, dinv, b3, fcw, fcb, out, N);
}